// round 7
// baseline (speedup 1.0000x reference)
#include <cuda_runtime.h>

#define GW      1024
#define GH      1024
#define W_OUT   4096
#define H_OUT   4096
#define NCH     4
#define GPLANE  (GH * GW)          // 1048576
#define OPLANE  (H_OUT * W_OUT)    // 16777216
#define TILE    1024               // period of the output in both axes

// Faithful fp32 replication of the reference coordinate chain:
//   f = (v - 511.5)/511.5 ; t = ((f + 1) * 0.5) * 1023 ; clip ; floor
__device__ __forceinline__ void axis_entry(int v, int* p0, float* pw) {
    float fv = __fadd_rn((float)v, -511.5f);
    float f  = __fdiv_rn(fv, 511.5f);
    float t  = __fmul_rn(__fmul_rn(__fadd_rn(f, 1.0f), 0.5f), 1023.0f);
    t = fminf(fmaxf(t, 0.0f), 1023.0f);
    float f0 = floorf(t);
    *p0 = (int)f0;
    *pw = __fadd_rn(t, -f0);
}

// Fused kernel, replica-parallel:
//   blockIdx.x = unique tile row (0..1023)
//   blockIdx.y = dy replica group (0..3)  — each group recomputes the quad
//                (cheap, L2-hit gathers) and stores its 4 dx replicas.
// 4096 CTAs x 256 threads = 1M threads -> high occupancy + deep store queue.
__global__ void __launch_bounds__(256) sample_rep_split_kernel(const float* __restrict__ grid,
                                                               const int* __restrict__ cs,
                                                               float* __restrict__ out) {
    const int y     = blockIdx.x;              // 0..1023 (unique tile row)
    const int dy    = blockIdx.y;              // 0..3    (replica row group)
    const int xbase = threadIdx.x * 4;         // 0..1020

    const int cs0 = cs[0];
    const int cs1 = cs[1];

    // y-axis entry (block-uniform)
    int y0; float wy;
    axis_entry((cs1 + y) & (GH - 1), &y0, &wy);
    const int   y1  = min(y0 + 1, GH - 1);
    const float omy = 1.0f - wy;

    // x-axis entries for the 4 pixels
    int   x0[4], x1[4];
    float wx[4], omx[4];
#pragma unroll
    for (int i = 0; i < 4; ++i) {
        axis_entry((cs0 + xbase + i) & (GW - 1), &x0[i], &wx[i]);
        x1[i]  = min(x0[i] + 1, GW - 1);
        omx[i] = 1.0f - wx[i];
    }

    const float* r0 = grid + y0 * GW;
    const float* r1 = grid + y1 * GW;

    // Compute 4 channels x 4 pixels
    float4 v[NCH];
#pragma unroll
    for (int c = 0; c < NCH; ++c) {
        const float* p0 = r0 + c * GPLANE;
        const float* p1 = r1 + c * GPLANE;
        float q[4];
#pragma unroll
        for (int i = 0; i < 4; ++i) {
            float v00 = __ldg(p0 + x0[i]);
            float v01 = __ldg(p0 + x1[i]);
            float v10 = __ldg(p1 + x0[i]);
            float v11 = __ldg(p1 + x1[i]);
            float top = v00 * omx[i] + v01 * wx[i];
            float bot = v10 * omx[i] + v11 * wx[i];
            q[i] = top * omy + bot * wy;
        }
        v[c] = make_float4(q[0], q[1], q[2], q[3]);
    }

    // Store this block's dy-replica row: 4 dx replicas per channel.
    const int obase = (dy * TILE + y) * W_OUT + xbase;   // float index; 16B-aligned
#pragma unroll
    for (int c = 0; c < NCH; ++c) {
        float4* po = (float4*)(out + c * OPLANE + obase);
        const float4 val = v[c];
#pragma unroll
        for (int dx = 0; dx < 4; ++dx) {
            po[dx * (TILE / 4)] = val;     // dx stride = 1024 floats = 256 float4
        }
    }
}

extern "C" void kernel_launch(void* const* d_in, const int* in_sizes, int n_in,
                              void* d_out, int out_size) {
    const float* grid = (const float*)d_in[0];
    const int*   cs   = (const int*)d_in[1];
    float*       out  = (float*)d_out;

    dim3 g(TILE, 4);
    sample_rep_split_kernel<<<g, 256>>>(grid, cs, out);
}

// round 9
// speedup vs baseline: 1.1332x; 1.1332x over previous
#include <cuda_runtime.h>

#define GW      1024
#define GH      1024
#define W_OUT   4096
#define H_OUT   4096
#define NCH     4
#define GPLANE  (GH * GW)          // 1048576
#define OPLANE  (H_OUT * W_OUT)    // 16777216
#define TILE    1024               // period of the output in both axes

// Faithful fp32 replication of the reference coordinate chain:
//   f = (v - 511.5)/511.5 ; t = ((f + 1) * 0.5) * 1023 ; clip ; floor
__device__ __forceinline__ void axis_entry(int v, int* p0, float* pw) {
    float fv = __fadd_rn((float)v, -511.5f);
    float f  = __fdiv_rn(fv, 511.5f);
    float t  = __fmul_rn(__fmul_rn(__fadd_rn(f, 1.0f), 0.5f), 1023.0f);
    t = fminf(fmaxf(t, 0.0f), 1023.0f);
    float f0 = floorf(t);
    *p0 = (int)f0;
    *pw = __fadd_rn(t, -f0);
}

// Fused single kernel, R3 structure: one thread per UNIQUE pixel (1024x1024),
// 4096 CTAs x 256 threads. Each thread computes its 4 channel values once
// (16 L2-resident gathers) and broadcasts each to 16 periodic replicas with
// plain coalesced scalar stores (64 per thread). Axis math computed inline
// (y-entry is block-uniform; x-entry one fdiv per thread).
__global__ void __launch_bounds__(256) sample_rep_fused_kernel(const float* __restrict__ grid,
                                                               const int* __restrict__ cs,
                                                               float* __restrict__ out) {
    const int t = blockIdx.x * blockDim.x + threadIdx.x;   // 0 .. 1048575
    const int x = t & (TILE - 1);
    const int y = t >> 10;          // block-uniform (256 threads span one row segment)

    const int cs0 = cs[0];
    const int cs1 = cs[1];

    int x0; float wx;
    axis_entry((cs0 + x) & (GW - 1), &x0, &wx);
    int y0; float wy;
    axis_entry((cs1 + y) & (GH - 1), &y0, &wy);   // warp-uniform

    const int   x1  = min(x0 + 1, GW - 1);
    const int   y1  = min(y0 + 1, GH - 1);
    const float omx = 1.0f - wx;
    const float omy = 1.0f - wy;

    const float* r0 = grid + y0 * GW;
    const float* r1 = grid + y1 * GW;

    float v[NCH];
#pragma unroll
    for (int c = 0; c < NCH; ++c) {
        const float* p0 = r0 + c * GPLANE;
        const float* p1 = r1 + c * GPLANE;
        float v00 = __ldg(p0 + x0);
        float v01 = __ldg(p0 + x1);
        float v10 = __ldg(p1 + x0);
        float v11 = __ldg(p1 + x1);
        float top = v00 * omx + v01 * wx;
        float bot = v10 * omx + v11 * wx;
        v[c] = top * omy + bot * wy;
    }

    // Replicate: 16 positions per channel; all stores fully coalesced
    // (lanes cover consecutive x), offsets compile-time constants.
    const int obase = y * W_OUT + x;
#pragma unroll
    for (int c = 0; c < NCH; ++c) {
        float* po = out + c * OPLANE + obase;
        const float val = v[c];
#pragma unroll
        for (int dy = 0; dy < 4; ++dy) {
#pragma unroll
            for (int dx = 0; dx < 4; ++dx) {
                po[dy * (TILE * W_OUT) + dx * TILE] = val;
            }
        }
    }
}

extern "C" void kernel_launch(void* const* d_in, const int* in_sizes, int n_in,
                              void* d_out, int out_size) {
    const float* grid = (const float*)d_in[0];
    const int*   cs   = (const int*)d_in[1];
    float*       out  = (float*)d_out;

    sample_rep_fused_kernel<<<(TILE * TILE) / 256, 256>>>(grid, cs, out);
}